// round 16
// baseline (speedup 1.0000x reference)
#include <cuda_runtime.h>
#include <cuda_fp16.h>
#include <cstdint>

// ============================================================================
// Problem constants (shapes fixed by setup_inputs)
// ============================================================================
static constexpr int BD   = 32;    // batch
static constexpr int VV   = 4;     // views
static constexpr int PP   = 784;   // patches
static constexpr int DD   = 768;   // model dim
static constexpr int TT   = VV * PP;           // 3136
static constexpr size_t TOK = (size_t)BD * TT; // 100352 tokens
static constexpr int HH   = 8;
static constexpr int DH   = 96;

// ============================================================================
// PTX helpers (portable sm_80+ subset only)
// ============================================================================
__device__ __forceinline__ uint32_t smem_to_u32(const void* smem_ptr) {
    uint32_t addr;
    asm("{ .reg .u64 tmp; cvta.to.shared.u64 tmp, %1; cvt.u32.u64 %0, tmp; }"
        : "=r"(addr) : "l"(smem_ptr));
    return addr;
}

__device__ __forceinline__ void cp_async16(uint32_t saddr, const void* gptr) {
    asm volatile("cp.async.cg.shared.global [%0], [%1], 16;"
                 :: "r"(saddr), "l"(gptr) : "memory");
}
__device__ __forceinline__ void cp_commit() {
    asm volatile("cp.async.commit_group;" ::: "memory");
}
template<int N>
__device__ __forceinline__ void cp_wait() {
    asm volatile("cp.async.wait_group %0;" :: "n"(N) : "memory");
}

__device__ __forceinline__ void ldsm_x4(uint32_t* r, uint32_t addr) {
    asm volatile("ldmatrix.sync.aligned.m8n8.x4.shared.b16 {%0,%1,%2,%3}, [%4];"
                 : "=r"(r[0]), "=r"(r[1]), "=r"(r[2]), "=r"(r[3]) : "r"(addr));
}

__device__ __forceinline__ void mma16816(float* c, const uint32_t* a, const uint32_t* b) {
    asm volatile(
        "mma.sync.aligned.m16n8k16.row.col.f32.f16.f16.f32 "
        "{%0,%1,%2,%3},{%4,%5,%6,%7},{%8,%9},{%0,%1,%2,%3};"
        : "+f"(c[0]), "+f"(c[1]), "+f"(c[2]), "+f"(c[3])
        : "r"(a[0]), "r"(a[1]), "r"(a[2]), "r"(a[3]), "r"(b[0]), "r"(b[1]));
}

// fast GELU: tanh form with MUFU.TANH (__tanhf, sm_75+).
__device__ __forceinline__ float gelu_fast(float x) {
    float t = __tanhf(0.7978845608f * (x + 0.044715f * x * x * x));
    return 0.5f * x * (1.0f + t);
}

// ============================================================================
// Device scratch (static __device__ arrays; cudaMalloc is forbidden)
// ============================================================================
__device__ __half g_h16 [TOK * DD];          // LN1 output (fp16)
__device__ __half g_qkv [TOK * 3 * DD];      // QKV (fp16)
__device__ __half g_o16 [TOK * DD];          // attention output (fp16)
__device__ __half g_x1  [TOK * DD];          // x + attn proj (fp16 residual stream)
__device__ __half g_h2  [TOK * DD];          // LN2 output (fp16)
__device__ __half g_ffn [TOK * 4 * DD];      // gelu(ffn1) (fp16)
__device__ __half g_wqkv[3 * DD * DD];
__device__ __half g_wout[DD * DD];
__device__ __half g_w1  [4 * DD * DD];
__device__ __half g_w2  [DD * 4 * DD];

// ============================================================================
// fp32 -> fp16 conversion of all four weight matrices in one launch
// ============================================================================
static constexpr int N_WQ = 3 * DD * DD;
static constexpr int N_WO = DD * DD;
static constexpr int N_W1 = 4 * DD * DD;
static constexpr int N_W2 = DD * 4 * DD;

__global__ void f2h_all_kernel(const float* __restrict__ wq_f, const float* __restrict__ wo_f,
                               const float* __restrict__ w1_f, const float* __restrict__ w2_f,
                               __half* __restrict__ wq, __half* __restrict__ wo,
                               __half* __restrict__ w1, __half* __restrict__ w2) {
    int total = N_WQ + N_WO + N_W1 + N_W2;
    int stride = gridDim.x * blockDim.x;
    for (int i = blockIdx.x * blockDim.x + threadIdx.x; i < total; i += stride) {
        int j = i;
        if (j < N_WQ) { wq[j] = __float2half(wq_f[j]); continue; }
        j -= N_WQ;
        if (j < N_WO) { wo[j] = __float2half(wo_f[j]); continue; }
        j -= N_WO;
        if (j < N_W1) { w1[j] = __float2half(w1_f[j]); continue; }
        j -= N_W1;
        w2[j] = __float2half(w2_f[j]);
    }
}

// ============================================================================
// LayerNorm (templated input type): -> fp16 output. One block (192) per row.
// ============================================================================
__device__ __forceinline__ float4 ld_row4(const float* p, size_t row, int t) {
    return reinterpret_cast<const float4*>(p + row * DD)[t];
}
__device__ __forceinline__ float4 ld_row4(const __half* p, size_t row, int t) {
    const __half2* h = reinterpret_cast<const __half2*>(p + row * DD) + 2 * t;
    float2 f0 = __half22float2(h[0]), f1 = __half22float2(h[1]);
    return make_float4(f0.x, f0.y, f1.x, f1.y);
}

template<typename T>
__global__ void __launch_bounds__(192) ln_kernel(
    const T* __restrict__ x, const float* __restrict__ w,
    const float* __restrict__ bb, __half* __restrict__ out)
{
    size_t row = blockIdx.x;
    int t = threadIdx.x;
    float4 v = ld_row4(x, row, t);
    float s  = v.x + v.y + v.z + v.w;
    float ss = v.x*v.x + v.y*v.y + v.z*v.z + v.w*v.w;
    #pragma unroll
    for (int off = 16; off; off >>= 1) {
        s  += __shfl_xor_sync(0xffffffffu, s,  off);
        ss += __shfl_xor_sync(0xffffffffu, ss, off);
    }
    __shared__ float rs_[6], rss_[6];
    int wi = t >> 5, ln = t & 31;
    if (ln == 0) { rs_[wi] = s; rss_[wi] = ss; }
    __syncthreads();
    float tot = 0.f, tot2 = 0.f;
    #pragma unroll
    for (int i = 0; i < 6; ++i) { tot += rs_[i]; tot2 += rss_[i]; }
    float mu  = tot * (1.0f / DD);
    float var = tot2 * (1.0f / DD) - mu * mu;
    float rstd = rsqrtf(var + 1e-5f);
    float4 wv = reinterpret_cast<const float4*>(w)[t];
    float4 bv = reinterpret_cast<const float4*>(bb)[t];
    __half2* op = reinterpret_cast<__half2*>(out + row * DD) + 2 * t;
    op[0] = __floats2half2_rn((v.x - mu) * rstd * wv.x + bv.x,
                              (v.y - mu) * rstd * wv.y + bv.y);
    op[1] = __floats2half2_rn((v.z - mu) * rstd * wv.z + bv.z,
                              (v.w - mu) * rstd * wv.w + bv.w);
}

// ============================================================================
// Cross-view attention, R16: one 256-thr block per (b, p).
// Streams the 4 full view-rows of qkv (4 x 2304 halves) into smem with
// coalesced uint4 loads (each byte fetched exactly once), 8 warps compute
// one head each from smem (math identical to the R15 version), outputs are
// staged in smem and written back as coalesced full rows.
// ============================================================================
__global__ void __launch_bounds__(256) attn_kernel(
    const __half* __restrict__ qkv, __half* __restrict__ o)
{
    __shared__ __half sq[4][3 * DD];   // 18432 B
    __shared__ __half so[4][DD];       //  6144 B

    int tid = threadIdx.x;
    int bp = blockIdx.x;               // 0 .. BD*PP-1
    int b  = bp / PP, p = bp - b * PP;
    size_t rowbase = (size_t)b * TT + p;

    // ---- coalesced load of 4 view rows: 4 x 288 uint4 = 1152 chunks ----
    #pragma unroll
    for (int i = 0; i < 5; ++i) {
        int idx = tid + i * 256;
        if (idx < 1152) {
            int v = idx / 288, cc = idx - v * 288;
            reinterpret_cast<uint4*>(sq[v])[cc] =
                reinterpret_cast<const uint4*>(qkv + (rowbase + (size_t)v * PP) * (3 * DD))[cc];
        }
    }
    __syncthreads();

    int h = tid >> 5, lane = tid & 31;   // warp h = head h

    float q[4][3], k[4][3], vv[4][3];
    #pragma unroll
    for (int v = 0; v < 4; ++v) {
        const __half* r = sq[v] + h * DH + lane;
        #pragma unroll
        for (int j = 0; j < 3; ++j) {
            q[v][j]  = __half2float(r[32 * j]);
            k[v][j]  = __half2float(r[DD + 32 * j]);
            vv[v][j] = __half2float(r[2 * DD + 32 * j]);
        }
    }
    float s[4][4];
    #pragma unroll
    for (int i = 0; i < 4; ++i) {
        #pragma unroll
        for (int j = 0; j < 4; ++j) {
            float acc = q[i][0]*k[j][0] + q[i][1]*k[j][1] + q[i][2]*k[j][2];
            #pragma unroll
            for (int off = 16; off; off >>= 1)
                acc += __shfl_xor_sync(0xffffffffu, acc, off);
            s[i][j] = acc * 0.1020620726f;   // 1/sqrt(96)
        }
    }
    #pragma unroll
    for (int i = 0; i < 4; ++i) {
        float m = fmaxf(fmaxf(s[i][0], s[i][1]), fmaxf(s[i][2], s[i][3]));
        float e0 = __expf(s[i][0] - m), e1 = __expf(s[i][1] - m);
        float e2 = __expf(s[i][2] - m), e3 = __expf(s[i][3] - m);
        float inv = 1.0f / (e0 + e1 + e2 + e3);
        __half* orow = so[i] + h * DH + lane;
        #pragma unroll
        for (int j = 0; j < 3; ++j) {
            float ov = (e0 * vv[0][j] + e1 * vv[1][j] + e2 * vv[2][j] + e3 * vv[3][j]) * inv;
            orow[32 * j] = __float2half(ov);
        }
    }
    __syncthreads();

    // ---- coalesced store of 4 output rows: 4 x 96 uint4 = 384 chunks ----
    #pragma unroll
    for (int i = 0; i < 2; ++i) {
        int idx = tid + i * 256;
        if (idx < 384) {
            int v = idx / 96, cc = idx - v * 96;
            reinterpret_cast<uint4*>(o + (rowbase + (size_t)v * PP) * DD)[cc] =
                reinterpret_cast<const uint4*>(so[v])[cc];
        }
    }
}

// ============================================================================
// HMMA GEMM:  C[M,N] = A[M,K](fp16) @ W[N,K]^T(fp16) + bias, epilogue
//   EPI 0: out fp16 = acc + bias
//   EPI 1: out fp16 = gelu_fast(acc + bias)        (tanh-form, MUFU.TANH)
//   EPI 2: out fp16 = acc + bias + resid(fp32)     (out-proj -> x1 fp16)
//   EPI 3: out fp32 = acc + bias + resid(fp16)     (FFN2 -> d_out)
// CTA tile 128x128, BK=64/stage, 128 thr = 4 warps of 64x64 warp tiles,
// 3-stage cp.async pipeline with cp_wait<1>, 2 CTAs/SM, padded SMEM LDS=72,
// ks-level fragment double-buffering. (Mainloop frozen.)
// ============================================================================
static constexpr int LDS_   = 72;            // halves per smem row (64 + 8 pad)
static constexpr int OSTG   = 128 * LDS_;    // halves per operand per stage
static constexpr int NSTAGE = 3;
static constexpr int GSMEM  = NSTAGE * 2 * OSTG * 2;   // 110592 bytes

template<int EPI>
__global__ void __launch_bounds__(128, 2) gemm_mma(
    const __half* __restrict__ A, const __half* __restrict__ W,
    const float* __restrict__ bias, const void* __restrict__ resid,
    void* __restrict__ outp, int K, int Ntot)
{
    extern __shared__ __half smem[];
    int tid = threadIdx.x;
    int lane = tid & 31, wid = tid >> 5;
    int m0 = blockIdx.y * 128;
    int n0 = blockIdx.x * 128;
    int wm = (wid & 1) * 64;       // warp row offset in tile
    int wn = (wid >> 1) * 64;      // warp col offset in tile

    // ---- async prefetch of one BK=64 chunk into stage s ----
    auto prefetch = [&](int kt, int s) {
        __half* st = smem + s * (2 * OSTG);
        int r0 = tid >> 3, cc = tid & 7;     // r0: 0..15, cc: 0..7
        #pragma unroll
        for (int h = 0; h < 8; ++h) {
            int r = r0 + h * 16;
            cp_async16(smem_to_u32(st + r * LDS_ + cc * 8),
                       A + (size_t)(m0 + r) * K + kt * 64 + cc * 8);
            cp_async16(smem_to_u32(st + OSTG + r * LDS_ + cc * 8),
                       W + (size_t)(n0 + r) * K + kt * 64 + cc * 8);
        }
    };

    float c[4][8][4];
    #pragma unroll
    for (int i = 0; i < 4; ++i)
        #pragma unroll
        for (int j = 0; j < 8; ++j)
            #pragma unroll
            for (int r = 0; r < 4; ++r) c[i][j][r] = 0.f;

    int NK = K >> 6;
    prefetch(0, 0); cp_commit();
    prefetch(1, 1); cp_commit();

    // ldmatrix lane addressing (constant per thread)
    int a_r  = wm + (lane & 15);
    int a_k  = (lane >> 4) << 3;
    int b_n  = wn + (lane & 7) + ((lane >> 4) << 3);
    int b_k  = ((lane >> 3) & 1) << 3;

    uint32_t a[2][4][4], b[2][4][4];   // double-buffered fragments

    int s_r = 0;   // stage to read this iteration
    int s_w = 2;   // stage to prefetch into (kt+2)
    #pragma unroll 1
    for (int kt = 0; kt < NK; ++kt) {
        cp_wait<1>();
        __syncthreads();
        if (kt + 2 < NK) prefetch(kt + 2, s_w);
        cp_commit();
        s_w = (s_w == 2) ? 0 : s_w + 1;

        const __half* sA = smem + s_r * (2 * OSTG);
        const __half* sB = sA + OSTG;
        s_r = (s_r == 2) ? 0 : s_r + 1;

        // preload fragments for ks=0
        #pragma unroll
        for (int ma = 0; ma < 4; ++ma)
            ldsm_x4(a[0][ma], smem_to_u32(sA + (a_r + ma * 16) * LDS_ + a_k));
        #pragma unroll
        for (int nb = 0; nb < 4; ++nb)
            ldsm_x4(b[0][nb], smem_to_u32(sB + (b_n + nb * 16) * LDS_ + b_k));

        #pragma unroll
        for (int ks = 0; ks < 4; ++ks) {
            int cur = ks & 1, nxt = cur ^ 1;
            if (ks < 3) {
                #pragma unroll
                for (int ma = 0; ma < 4; ++ma)
                    ldsm_x4(a[nxt][ma],
                            smem_to_u32(sA + (a_r + ma * 16) * LDS_ + (ks + 1) * 16 + a_k));
                #pragma unroll
                for (int nb = 0; nb < 4; ++nb)
                    ldsm_x4(b[nxt][nb],
                            smem_to_u32(sB + (b_n + nb * 16) * LDS_ + (ks + 1) * 16 + b_k));
            }
            #pragma unroll
            for (int ma = 0; ma < 4; ++ma)
                #pragma unroll
                for (int na = 0; na < 8; ++na)
                    mma16816(c[ma][na], a[cur][ma], b[cur][na >> 1] + (na & 1) * 2);
        }
    }

    // ---- epilogue straight from registers ----
    #pragma unroll
    for (int ma = 0; ma < 4; ++ma) {
        #pragma unroll
        for (int na = 0; na < 8; ++na) {
            int row = m0 + wm + ma * 16 + (lane >> 2);
            int col = n0 + wn + na * 8 + ((lane & 3) << 1);
            float b0 = bias[col], b1 = bias[col + 1];
            #pragma unroll
            for (int h = 0; h < 2; ++h) {
                size_t off = (size_t)(row + h * 8) * Ntot + col;
                float v0 = c[ma][na][2 * h + 0] + b0;
                float v1 = c[ma][na][2 * h + 1] + b1;
                if (EPI == 1) {
                    v0 = gelu_fast(v0);
                    v1 = gelu_fast(v1);
                }
                if (EPI == 2) {
                    float2 r2 = *reinterpret_cast<const float2*>(
                        reinterpret_cast<const float*>(resid) + off);
                    *reinterpret_cast<__half2*>(reinterpret_cast<__half*>(outp) + off) =
                        __floats2half2_rn(v0 + r2.x, v1 + r2.y);
                } else if (EPI == 3) {
                    __half2 rh = *reinterpret_cast<const __half2*>(
                        reinterpret_cast<const __half*>(resid) + off);
                    float2 r2 = __half22float2(rh);
                    float2 o2 = make_float2(v0 + r2.x, v1 + r2.y);
                    *reinterpret_cast<float2*>(reinterpret_cast<float*>(outp) + off) = o2;
                } else {
                    *reinterpret_cast<__half2*>(reinterpret_cast<__half*>(outp) + off) =
                        __floats2half2_rn(v0, v1);
                }
            }
        }
    }
}

// ============================================================================
// Host launch
// ============================================================================
extern "C" void kernel_launch(void* const* d_in, const int* in_sizes, int n_in,
                              void* d_out, int out_size)
{
    const float* x        = (const float*)d_in[0];
    // d_in[1] = num_views (scalar, fixed = 4)
    const float* norm1_w  = (const float*)d_in[2];
    const float* norm1_b  = (const float*)d_in[3];
    const float* in_proj_w= (const float*)d_in[4];
    const float* in_proj_b= (const float*)d_in[5];
    const float* out_w    = (const float*)d_in[6];
    const float* out_b    = (const float*)d_in[7];
    const float* norm2_w  = (const float*)d_in[8];
    const float* norm2_b  = (const float*)d_in[9];
    const float* ffn_w1   = (const float*)d_in[10];
    const float* ffn_b1   = (const float*)d_in[11];
    const float* ffn_w2   = (const float*)d_in[12];
    const float* ffn_b2   = (const float*)d_in[13];

    __half *h16, *qkv, *o16, *x1, *h2, *ffn, *wq, *wo, *w1, *w2;
    cudaGetSymbolAddress((void**)&h16, g_h16);
    cudaGetSymbolAddress((void**)&qkv, g_qkv);
    cudaGetSymbolAddress((void**)&o16, g_o16);
    cudaGetSymbolAddress((void**)&x1,  g_x1);
    cudaGetSymbolAddress((void**)&h2,  g_h2);
    cudaGetSymbolAddress((void**)&ffn, g_ffn);
    cudaGetSymbolAddress((void**)&wq,  g_wqkv);
    cudaGetSymbolAddress((void**)&wo,  g_wout);
    cudaGetSymbolAddress((void**)&w1,  g_w1);
    cudaGetSymbolAddress((void**)&w2,  g_w2);

    cudaFuncSetAttribute(gemm_mma<0>, cudaFuncAttributeMaxDynamicSharedMemorySize, GSMEM);
    cudaFuncSetAttribute(gemm_mma<1>, cudaFuncAttributeMaxDynamicSharedMemorySize, GSMEM);
    cudaFuncSetAttribute(gemm_mma<2>, cudaFuncAttributeMaxDynamicSharedMemorySize, GSMEM);
    cudaFuncSetAttribute(gemm_mma<3>, cudaFuncAttributeMaxDynamicSharedMemorySize, GSMEM);

    // weight conversion fp32 -> fp16 (single launch)
    f2h_all_kernel<<<8192, 256>>>(in_proj_w, out_w, ffn_w1, ffn_w2, wq, wo, w1, w2);

    // LN1 (fp32 in)
    ln_kernel<float><<<(unsigned)TOK, 192>>>(x, norm1_w, norm1_b, h16);

    // QKV = LN1 @ Wqkv^T + b
    gemm_mma<0><<<dim3(3 * DD / 128, (unsigned)(TOK / 128)), 128, GSMEM>>>(
        h16, wq, in_proj_b, nullptr, qkv, DD, 3 * DD);

    // cross-view attention (block per (b,p), smem-staged, coalesced)
    attn_kernel<<<BD * PP, 256>>>(qkv, o16);

    // out proj + fp32 residual -> x1 (fp16)
    gemm_mma<2><<<dim3(DD / 128, (unsigned)(TOK / 128)), 128, GSMEM>>>(
        o16, wo, out_b, x, x1, DD, DD);

    // LN2 (fp16 in)
    ln_kernel<__half><<<(unsigned)TOK, 192>>>(x1, norm2_w, norm2_b, h2);

    // FFN1 + fast GELU (tanh form)
    gemm_mma<1><<<dim3(4 * DD / 128, (unsigned)(TOK / 128)), 128, GSMEM>>>(
        h2, w1, ffn_b1, nullptr, ffn, DD, 4 * DD);

    // FFN2 + fp16 residual -> d_out (fp32)
    gemm_mma<3><<<dim3(DD / 128, (unsigned)(TOK / 128)), 128, GSMEM>>>(
        ffn, w2, ffn_b2, x1, (float*)d_out, 4 * DD, DD);

    (void)in_sizes; (void)n_in; (void)out_size;
}

// round 17
// speedup vs baseline: 1.0164x; 1.0164x over previous
#include <cuda_runtime.h>
#include <cuda_fp16.h>
#include <cstdint>

// ============================================================================
// Problem constants (shapes fixed by setup_inputs)
// ============================================================================
static constexpr int BD   = 32;    // batch
static constexpr int VV   = 4;     // views
static constexpr int PP   = 784;   // patches
static constexpr int DD   = 768;   // model dim
static constexpr int TT   = VV * PP;           // 3136
static constexpr size_t TOK = (size_t)BD * TT; // 100352 tokens
static constexpr int HH   = 8;
static constexpr int DH   = 96;

// ============================================================================
// PTX helpers (portable sm_80+ subset only)
// ============================================================================
__device__ __forceinline__ uint32_t smem_to_u32(const void* smem_ptr) {
    uint32_t addr;
    asm("{ .reg .u64 tmp; cvta.to.shared.u64 tmp, %1; cvt.u32.u64 %0, tmp; }"
        : "=r"(addr) : "l"(smem_ptr));
    return addr;
}

__device__ __forceinline__ void cp_async16(uint32_t saddr, const void* gptr) {
    asm volatile("cp.async.cg.shared.global [%0], [%1], 16;"
                 :: "r"(saddr), "l"(gptr) : "memory");
}
__device__ __forceinline__ void cp_commit() {
    asm volatile("cp.async.commit_group;" ::: "memory");
}
template<int N>
__device__ __forceinline__ void cp_wait() {
    asm volatile("cp.async.wait_group %0;" :: "n"(N) : "memory");
}

__device__ __forceinline__ void ldsm_x4(uint32_t* r, uint32_t addr) {
    asm volatile("ldmatrix.sync.aligned.m8n8.x4.shared.b16 {%0,%1,%2,%3}, [%4];"
                 : "=r"(r[0]), "=r"(r[1]), "=r"(r[2]), "=r"(r[3]) : "r"(addr));
}

__device__ __forceinline__ void mma16816(float* c, const uint32_t* a, const uint32_t* b) {
    asm volatile(
        "mma.sync.aligned.m16n8k16.row.col.f32.f16.f16.f32 "
        "{%0,%1,%2,%3},{%4,%5,%6,%7},{%8,%9},{%0,%1,%2,%3};"
        : "+f"(c[0]), "+f"(c[1]), "+f"(c[2]), "+f"(c[3])
        : "r"(a[0]), "r"(a[1]), "r"(a[2]), "r"(a[3]), "r"(b[0]), "r"(b[1]));
}

// fast GELU: tanh form with MUFU.TANH (__tanhf, sm_75+).
__device__ __forceinline__ float gelu_fast(float x) {
    float t = __tanhf(0.7978845608f * (x + 0.044715f * x * x * x));
    return 0.5f * x * (1.0f + t);
}

// ============================================================================
// Device scratch (static __device__ arrays; cudaMalloc is forbidden)
// ============================================================================
__device__ __half g_h16 [TOK * DD];          // LN1 output (fp16)
__device__ __half g_qkv [TOK * 3 * DD];      // QKV (fp16)
__device__ __half g_o16 [TOK * DD];          // attention output (fp16)
__device__ __half g_x1  [TOK * DD];          // x + attn proj (fp16 residual stream)
__device__ __half g_h2  [TOK * DD];          // LN2 output (fp16)
__device__ __half g_ffn [TOK * 4 * DD];      // gelu(ffn1) (fp16)
__device__ __half g_wqkv[3 * DD * DD];
__device__ __half g_wout[DD * DD];
__device__ __half g_w1  [4 * DD * DD];
__device__ __half g_w2  [DD * 4 * DD];

// ============================================================================
// fp32 -> fp16 conversion of all four weight matrices in one launch
// ============================================================================
static constexpr int N_WQ = 3 * DD * DD;
static constexpr int N_WO = DD * DD;
static constexpr int N_W1 = 4 * DD * DD;
static constexpr int N_W2 = DD * 4 * DD;

__global__ void f2h_all_kernel(const float* __restrict__ wq_f, const float* __restrict__ wo_f,
                               const float* __restrict__ w1_f, const float* __restrict__ w2_f,
                               __half* __restrict__ wq, __half* __restrict__ wo,
                               __half* __restrict__ w1, __half* __restrict__ w2) {
    int total = N_WQ + N_WO + N_W1 + N_W2;
    int stride = gridDim.x * blockDim.x;
    for (int i = blockIdx.x * blockDim.x + threadIdx.x; i < total; i += stride) {
        int j = i;
        if (j < N_WQ) { wq[j] = __float2half(wq_f[j]); continue; }
        j -= N_WQ;
        if (j < N_WO) { wo[j] = __float2half(wo_f[j]); continue; }
        j -= N_WO;
        if (j < N_W1) { w1[j] = __float2half(w1_f[j]); continue; }
        j -= N_W1;
        w2[j] = __float2half(w2_f[j]);
    }
}

// ============================================================================
// LayerNorm, R17: warp-per-row (no smem, no block barrier). 256 thr = 8 rows
// per block. Each lane holds 24 values (6 x float4, coalesced 512B segments).
// ============================================================================
__device__ __forceinline__ float4 ld_row4(const float* p, size_t row, int t) {
    return reinterpret_cast<const float4*>(p + row * DD)[t];
}
__device__ __forceinline__ float4 ld_row4(const __half* p, size_t row, int t) {
    const __half2* h = reinterpret_cast<const __half2*>(p + row * DD) + 2 * t;
    float2 f0 = __half22float2(h[0]), f1 = __half22float2(h[1]);
    return make_float4(f0.x, f0.y, f1.x, f1.y);
}

template<typename T>
__global__ void __launch_bounds__(256) ln_kernel(
    const T* __restrict__ x, const float* __restrict__ w,
    const float* __restrict__ bb, __half* __restrict__ out)
{
    int warp = threadIdx.x >> 5, lane = threadIdx.x & 31;
    size_t row = (size_t)blockIdx.x * 8 + warp;

    float4 v[6];
    #pragma unroll
    for (int k = 0; k < 6; ++k)
        v[k] = ld_row4(x, row, lane + 32 * k);

    float s = 0.f, ss = 0.f;
    #pragma unroll
    for (int k = 0; k < 6; ++k) {
        s  += v[k].x + v[k].y + v[k].z + v[k].w;
        ss += v[k].x*v[k].x + v[k].y*v[k].y + v[k].z*v[k].z + v[k].w*v[k].w;
    }
    #pragma unroll
    for (int off = 16; off; off >>= 1) {
        s  += __shfl_xor_sync(0xffffffffu, s,  off);
        ss += __shfl_xor_sync(0xffffffffu, ss, off);
    }
    float mu  = s * (1.0f / DD);
    float var = ss * (1.0f / DD) - mu * mu;
    float rstd = rsqrtf(var + 1e-5f);

    __half2* op = reinterpret_cast<__half2*>(out + row * DD);
    #pragma unroll
    for (int k = 0; k < 6; ++k) {
        int c4 = lane + 32 * k;
        float4 wv = reinterpret_cast<const float4*>(w)[c4];
        float4 bv = reinterpret_cast<const float4*>(bb)[c4];
        op[c4 * 2 + 0] = __floats2half2_rn((v[k].x - mu) * rstd * wv.x + bv.x,
                                           (v[k].y - mu) * rstd * wv.y + bv.y);
        op[c4 * 2 + 1] = __floats2half2_rn((v[k].z - mu) * rstd * wv.z + bv.z,
                                           (v[k].w - mu) * rstd * wv.w + bv.w);
    }
}

// ============================================================================
// Cross-view attention: one warp per (b, p, head). V=4, dh=96 (3 dims/lane).
// R15 direct version — measured at its DRAM floor (128 µs); R16's smem-staged
// variant regressed (staging ALU+barriers cost more than coalescing saved).
// PERMANENTLY FROZEN.
// ============================================================================
__global__ void __launch_bounds__(128) attn_kernel(
    const __half* __restrict__ qkv, __half* __restrict__ o)
{
    int wid = threadIdx.x >> 5, lane = threadIdx.x & 31;
    int g  = blockIdx.x * 4 + wid;
    int h  = g & 7;
    int bp = g >> 3;
    int b  = bp / PP, p = bp - b * PP;
    size_t rowbase = (size_t)b * TT + p;

    float q[4][3], k[4][3], vv[4][3];
    #pragma unroll
    for (int v = 0; v < 4; ++v) {
        const __half* r = qkv + (rowbase + (size_t)v * PP) * (3 * DD) + h * DH + lane;
        #pragma unroll
        for (int j = 0; j < 3; ++j) {
            q[v][j]  = __half2float(r[32 * j]);
            k[v][j]  = __half2float(r[DD + 32 * j]);
            vv[v][j] = __half2float(r[2 * DD + 32 * j]);
        }
    }
    float s[4][4];
    #pragma unroll
    for (int i = 0; i < 4; ++i) {
        #pragma unroll
        for (int j = 0; j < 4; ++j) {
            float acc = q[i][0]*k[j][0] + q[i][1]*k[j][1] + q[i][2]*k[j][2];
            #pragma unroll
            for (int off = 16; off; off >>= 1)
                acc += __shfl_xor_sync(0xffffffffu, acc, off);
            s[i][j] = acc * 0.1020620726f;   // 1/sqrt(96)
        }
    }
    #pragma unroll
    for (int i = 0; i < 4; ++i) {
        float m = fmaxf(fmaxf(s[i][0], s[i][1]), fmaxf(s[i][2], s[i][3]));
        float e0 = __expf(s[i][0] - m), e1 = __expf(s[i][1] - m);
        float e2 = __expf(s[i][2] - m), e3 = __expf(s[i][3] - m);
        float inv = 1.0f / (e0 + e1 + e2 + e3);
        __half* orow = o + (rowbase + (size_t)i * PP) * DD + h * DH + lane;
        #pragma unroll
        for (int j = 0; j < 3; ++j) {
            float ov = (e0 * vv[0][j] + e1 * vv[1][j] + e2 * vv[2][j] + e3 * vv[3][j]) * inv;
            orow[32 * j] = __float2half(ov);
        }
    }
}

// ============================================================================
// HMMA GEMM:  C[M,N] = A[M,K](fp16) @ W[N,K]^T(fp16) + bias, epilogue
//   EPI 0: out fp16 = acc + bias
//   EPI 1: out fp16 = gelu_fast(acc + bias)        (tanh-form, MUFU.TANH)
//   EPI 2: out fp16 = acc + bias + resid(fp32)     (out-proj -> x1 fp16)
//   EPI 3: out fp32 = acc + bias + resid(fp16)     (FFN2 -> d_out)
// CTA tile 128x128, BK=64/stage, 128 thr = 4 warps of 64x64 warp tiles,
// 3-stage cp.async pipeline with cp_wait<1>, 2 CTAs/SM, padded SMEM LDS=72,
// ks-level fragment double-buffering. (Mainloop frozen.)
// ============================================================================
static constexpr int LDS_   = 72;            // halves per smem row (64 + 8 pad)
static constexpr int OSTG   = 128 * LDS_;    // halves per operand per stage
static constexpr int NSTAGE = 3;
static constexpr int GSMEM  = NSTAGE * 2 * OSTG * 2;   // 110592 bytes

template<int EPI>
__global__ void __launch_bounds__(128, 2) gemm_mma(
    const __half* __restrict__ A, const __half* __restrict__ W,
    const float* __restrict__ bias, const void* __restrict__ resid,
    void* __restrict__ outp, int K, int Ntot)
{
    extern __shared__ __half smem[];
    int tid = threadIdx.x;
    int lane = tid & 31, wid = tid >> 5;
    int m0 = blockIdx.y * 128;
    int n0 = blockIdx.x * 128;
    int wm = (wid & 1) * 64;       // warp row offset in tile
    int wn = (wid >> 1) * 64;      // warp col offset in tile

    // ---- async prefetch of one BK=64 chunk into stage s ----
    auto prefetch = [&](int kt, int s) {
        __half* st = smem + s * (2 * OSTG);
        int r0 = tid >> 3, cc = tid & 7;     // r0: 0..15, cc: 0..7
        #pragma unroll
        for (int h = 0; h < 8; ++h) {
            int r = r0 + h * 16;
            cp_async16(smem_to_u32(st + r * LDS_ + cc * 8),
                       A + (size_t)(m0 + r) * K + kt * 64 + cc * 8);
            cp_async16(smem_to_u32(st + OSTG + r * LDS_ + cc * 8),
                       W + (size_t)(n0 + r) * K + kt * 64 + cc * 8);
        }
    };

    float c[4][8][4];
    #pragma unroll
    for (int i = 0; i < 4; ++i)
        #pragma unroll
        for (int j = 0; j < 8; ++j)
            #pragma unroll
            for (int r = 0; r < 4; ++r) c[i][j][r] = 0.f;

    int NK = K >> 6;
    prefetch(0, 0); cp_commit();
    prefetch(1, 1); cp_commit();

    // ldmatrix lane addressing (constant per thread)
    int a_r  = wm + (lane & 15);
    int a_k  = (lane >> 4) << 3;
    int b_n  = wn + (lane & 7) + ((lane >> 4) << 3);
    int b_k  = ((lane >> 3) & 1) << 3;

    uint32_t a[2][4][4], b[2][4][4];   // double-buffered fragments

    int s_r = 0;   // stage to read this iteration
    int s_w = 2;   // stage to prefetch into (kt+2)
    #pragma unroll 1
    for (int kt = 0; kt < NK; ++kt) {
        cp_wait<1>();
        __syncthreads();
        if (kt + 2 < NK) prefetch(kt + 2, s_w);
        cp_commit();
        s_w = (s_w == 2) ? 0 : s_w + 1;

        const __half* sA = smem + s_r * (2 * OSTG);
        const __half* sB = sA + OSTG;
        s_r = (s_r == 2) ? 0 : s_r + 1;

        // preload fragments for ks=0
        #pragma unroll
        for (int ma = 0; ma < 4; ++ma)
            ldsm_x4(a[0][ma], smem_to_u32(sA + (a_r + ma * 16) * LDS_ + a_k));
        #pragma unroll
        for (int nb = 0; nb < 4; ++nb)
            ldsm_x4(b[0][nb], smem_to_u32(sB + (b_n + nb * 16) * LDS_ + b_k));

        #pragma unroll
        for (int ks = 0; ks < 4; ++ks) {
            int cur = ks & 1, nxt = cur ^ 1;
            if (ks < 3) {
                #pragma unroll
                for (int ma = 0; ma < 4; ++ma)
                    ldsm_x4(a[nxt][ma],
                            smem_to_u32(sA + (a_r + ma * 16) * LDS_ + (ks + 1) * 16 + a_k));
                #pragma unroll
                for (int nb = 0; nb < 4; ++nb)
                    ldsm_x4(b[nxt][nb],
                            smem_to_u32(sB + (b_n + nb * 16) * LDS_ + (ks + 1) * 16 + b_k));
            }
            #pragma unroll
            for (int ma = 0; ma < 4; ++ma)
                #pragma unroll
                for (int na = 0; na < 8; ++na)
                    mma16816(c[ma][na], a[cur][ma], b[cur][na >> 1] + (na & 1) * 2);
        }
    }

    // ---- epilogue straight from registers ----
    #pragma unroll
    for (int ma = 0; ma < 4; ++ma) {
        #pragma unroll
        for (int na = 0; na < 8; ++na) {
            int row = m0 + wm + ma * 16 + (lane >> 2);
            int col = n0 + wn + na * 8 + ((lane & 3) << 1);
            float b0 = bias[col], b1 = bias[col + 1];
            #pragma unroll
            for (int h = 0; h < 2; ++h) {
                size_t off = (size_t)(row + h * 8) * Ntot + col;
                float v0 = c[ma][na][2 * h + 0] + b0;
                float v1 = c[ma][na][2 * h + 1] + b1;
                if (EPI == 1) {
                    v0 = gelu_fast(v0);
                    v1 = gelu_fast(v1);
                }
                if (EPI == 2) {
                    float2 r2 = *reinterpret_cast<const float2*>(
                        reinterpret_cast<const float*>(resid) + off);
                    *reinterpret_cast<__half2*>(reinterpret_cast<__half*>(outp) + off) =
                        __floats2half2_rn(v0 + r2.x, v1 + r2.y);
                } else if (EPI == 3) {
                    __half2 rh = *reinterpret_cast<const __half2*>(
                        reinterpret_cast<const __half*>(resid) + off);
                    float2 r2 = __half22float2(rh);
                    float2 o2 = make_float2(v0 + r2.x, v1 + r2.y);
                    *reinterpret_cast<float2*>(reinterpret_cast<float*>(outp) + off) = o2;
                } else {
                    *reinterpret_cast<__half2*>(reinterpret_cast<__half*>(outp) + off) =
                        __floats2half2_rn(v0, v1);
                }
            }
        }
    }
}

// ============================================================================
// Host launch
// ============================================================================
extern "C" void kernel_launch(void* const* d_in, const int* in_sizes, int n_in,
                              void* d_out, int out_size)
{
    const float* x        = (const float*)d_in[0];
    // d_in[1] = num_views (scalar, fixed = 4)
    const float* norm1_w  = (const float*)d_in[2];
    const float* norm1_b  = (const float*)d_in[3];
    const float* in_proj_w= (const float*)d_in[4];
    const float* in_proj_b= (const float*)d_in[5];
    const float* out_w    = (const float*)d_in[6];
    const float* out_b    = (const float*)d_in[7];
    const float* norm2_w  = (const float*)d_in[8];
    const float* norm2_b  = (const float*)d_in[9];
    const float* ffn_w1   = (const float*)d_in[10];
    const float* ffn_b1   = (const float*)d_in[11];
    const float* ffn_w2   = (const float*)d_in[12];
    const float* ffn_b2   = (const float*)d_in[13];

    __half *h16, *qkv, *o16, *x1, *h2, *ffn, *wq, *wo, *w1, *w2;
    cudaGetSymbolAddress((void**)&h16, g_h16);
    cudaGetSymbolAddress((void**)&qkv, g_qkv);
    cudaGetSymbolAddress((void**)&o16, g_o16);
    cudaGetSymbolAddress((void**)&x1,  g_x1);
    cudaGetSymbolAddress((void**)&h2,  g_h2);
    cudaGetSymbolAddress((void**)&ffn, g_ffn);
    cudaGetSymbolAddress((void**)&wq,  g_wqkv);
    cudaGetSymbolAddress((void**)&wo,  g_wout);
    cudaGetSymbolAddress((void**)&w1,  g_w1);
    cudaGetSymbolAddress((void**)&w2,  g_w2);

    cudaFuncSetAttribute(gemm_mma<0>, cudaFuncAttributeMaxDynamicSharedMemorySize, GSMEM);
    cudaFuncSetAttribute(gemm_mma<1>, cudaFuncAttributeMaxDynamicSharedMemorySize, GSMEM);
    cudaFuncSetAttribute(gemm_mma<2>, cudaFuncAttributeMaxDynamicSharedMemorySize, GSMEM);
    cudaFuncSetAttribute(gemm_mma<3>, cudaFuncAttributeMaxDynamicSharedMemorySize, GSMEM);

    // weight conversion fp32 -> fp16 (single launch)
    f2h_all_kernel<<<8192, 256>>>(in_proj_w, out_w, ffn_w1, ffn_w2, wq, wo, w1, w2);

    // LN1 (fp32 in), warp-per-row: 8 rows per 256-thr block
    ln_kernel<float><<<(unsigned)(TOK / 8), 256>>>(x, norm1_w, norm1_b, h16);

    // QKV = LN1 @ Wqkv^T + b
    gemm_mma<0><<<dim3(3 * DD / 128, (unsigned)(TOK / 128)), 128, GSMEM>>>(
        h16, wq, in_proj_b, nullptr, qkv, DD, 3 * DD);

    // cross-view attention (R15 direct version)
    attn_kernel<<<(BD * PP * HH) / 4, 128>>>(qkv, o16);

    // out proj + fp32 residual -> x1 (fp16)
    gemm_mma<2><<<dim3(DD / 128, (unsigned)(TOK / 128)), 128, GSMEM>>>(
        o16, wo, out_b, x, x1, DD, DD);

    // LN2 (fp16 in), warp-per-row
    ln_kernel<__half><<<(unsigned)(TOK / 8), 256>>>(x1, norm2_w, norm2_b, h2);

    // FFN1 + fast GELU (tanh form)
    gemm_mma<1><<<dim3(4 * DD / 128, (unsigned)(TOK / 128)), 128, GSMEM>>>(
        h2, w1, ffn_b1, nullptr, ffn, DD, 4 * DD);

    // FFN2 + fp16 residual -> d_out (fp32)
    gemm_mma<3><<<dim3(DD / 128, (unsigned)(TOK / 128)), 128, GSMEM>>>(
        ffn, w2, ffn_b2, x1, (float*)d_out, 4 * DD, DD);

    (void)in_sizes; (void)n_in; (void)out_size;
}